// round 15
// baseline (speedup 1.0000x reference)
#include <cuda_runtime.h>
#include <cuda_bf16.h>
#include <math.h>
#include <stdint.h>

#define N_SAMPLES 16384
#define F_DIM 64
#define K_BINS 32
#define M_DIM 2048
#define C_DIM 128
#define EPSV 1e-8f

// ---- k1 dynamic smem layout (bytes) ----
// RAW: 2 x [64][128] fp32 = 65536 (Apack [32][136] u32 aliases current buffer)
// B:   2 x [128][144B]    = 36864 (Bt[c][qpair] rows: 32 u32 + 4 pad)
// Y:   2 x 64 fp32        = 512
#define SM_RAW   0
#define SM_B     65536
#define SM_Y     102400
#define SM_TOTAL 102912

__device__ float    gS[M_DIM * C_DIM];
__device__ float    gMass[M_DIM];
__device__ float    gWy[M_DIM];
__device__ float    gYsq[N_SAMPLES];
__device__ uint32_t gTpack[(N_SAMPLES / 2) * C_DIM];   // [np][c]
__device__ uint32_t gT2[C_DIM * (N_SAMPLES / 2)];      // [c][np] (transposed)
__device__ float    gOut[4];
__device__ int      gDone;

__device__ __forceinline__ float warp_sum(float v) {
    v += __shfl_xor_sync(0xffffffffu, v, 16);
    v += __shfl_xor_sync(0xffffffffu, v, 8);
    v += __shfl_xor_sync(0xffffffffu, v, 4);
    v += __shfl_xor_sync(0xffffffffu, v, 2);
    v += __shfl_xor_sync(0xffffffffu, v, 1);
    return v;
}
__device__ __forceinline__ uint32_t pack_bf16x2(float lo, float hi) {
    __nv_bfloat162 t = __floats2bfloat162_rn(lo, hi);
    return *reinterpret_cast<uint32_t*>(&t);
}
__device__ __forceinline__ void mma_bf16(float* d, const uint32_t* a,
                                         uint32_t b0, uint32_t b1) {
    asm volatile(
        "mma.sync.aligned.m16n8k16.row.col.f32.bf16.bf16.f32 "
        "{%0,%1,%2,%3}, {%4,%5,%6,%7}, {%8,%9}, {%0,%1,%2,%3};\n"
        : "+f"(d[0]), "+f"(d[1]), "+f"(d[2]), "+f"(d[3])
        : "r"(a[0]), "r"(a[1]), "r"(a[2]), "r"(a[3]), "r"(b0), "r"(b1));
}
__device__ __forceinline__ void ldm_x4(uint32_t* r, uint32_t addr) {
    asm volatile("ldmatrix.sync.aligned.m8n8.x4.shared.b16 {%0,%1,%2,%3}, [%4];"
        : "=r"(r[0]), "=r"(r[1]), "=r"(r[2]), "=r"(r[3]) : "r"(addr));
}
__device__ __forceinline__ void cp16(uint32_t dst, const void* src) {
    asm volatile("cp.async.cg.shared.global [%0], [%1], 16;\n" :: "r"(dst), "l"(src));
}

// ---------------- Kernel 0: zero + y_sq + prepack teacher ----------------
__global__ void k0_init(const float* __restrict__ teacher) {
    int tid = threadIdx.x;
    int idx = blockIdx.x * 256 + tid;            // 0 .. 524287
    if (idx < M_DIM * C_DIM) gS[idx] = 0.0f;
    if (idx < M_DIM) { gMass[idx] = 0.0f; gWy[idx] = 0.0f; }
    if (idx < 4) gOut[idx] = 0.0f;
    if (idx == 4) gDone = 0;

    int n = idx >> 5;
    int lane = tid & 31;
    if (n < N_SAMPLES) {
        float4 v = reinterpret_cast<const float4*>(teacher)[n * 32 + lane];
        float s = v.x * v.x + v.y * v.y + v.z * v.z + v.w * v.w;
        s = warp_sum(s);
        if (lane == 0) gYsq[n] = s;
    }

#pragma unroll
    for (int j = 0; j < 2; ++j) {
        int w = idx + j * 524288;
        int np = w >> 7;
        int c = w & 127;
        gTpack[w] = pack_bf16x2(teacher[(2 * np) * C_DIM + c],
                                teacher[(2 * np + 1) * C_DIM + c]);
    }
}

// ---------------- Kernel 0b: transpose gTpack[np][c] -> gT2[c][np] ----------------
__global__ void __launch_bounds__(256) k0b_transpose() {
    __shared__ uint32_t Ts[32][33];
    int tid = threadIdx.x;
    int b = blockIdx.x;              // 1024 blocks
    int npb = b & 255, cb = b >> 8;
    int np0 = npb * 32, c0 = cb * 32;
#pragma unroll
    for (int r = 0; r < 4; ++r) {
        int idx = tid + 256 * r;
        int i = idx >> 5, j = idx & 31;
        Ts[i][j] = gTpack[(size_t)(np0 + i) * C_DIM + c0 + j];
    }
    __syncthreads();
#pragma unroll
    for (int r = 0; r < 4; ++r) {
        int idx = tid + 256 * r;
        int j = idx >> 5, i = idx & 31;
        gT2[(size_t)(c0 + j) * (N_SAMPLES / 2) + np0 + i] = Ts[i][j];
    }
}

// ---------------- Kernel 1: balanced, convert-pass, ldmatrix-B GEMM ----------------
// grid 296 = 148 SMs x 2. m-tile = bid&15; chunk ranges partition 256 chunks evenly.
__global__ void __launch_bounds__(256, 2)
k1_main(const float* __restrict__ membership) {
    extern __shared__ char smem[];
    uint32_t sb = (uint32_t)__cvta_generic_to_shared(smem);

    int tid = threadIdx.x;
    int mt = blockIdx.x & 15;
    int sp = blockIdx.x >> 4;
    int m0 = mt * 128;

    int cbase, ccnt;
    if (mt < 8) {   // 19 CTAs per m-tile: 9x14 + 10x13 = 256
        cbase = sp * 13 + min(sp, 9);
        ccnt = 13 + (sp < 9 ? 1 : 0);
    } else {        // 18 CTAs per m-tile: 4x15 + 14x14 = 256
        cbase = sp * 14 + min(sp, 4);
        ccnt = 14 + (sp < 4 ? 1 : 0);
    }

    int w = tid >> 5, lane = tid & 31;
    int m_off = (w & 3) * 32;
    int c_off = (w >> 2) * 64;
    int lr = lane >> 2, lc = lane & 3;

    // convert-pass coords
    int m4 = tid & 31;
    int qg = tid >> 5;

    float d[2][8][4];
#pragma unroll
    for (int i = 0; i < 2; ++i)
#pragma unroll
        for (int j = 0; j < 8; ++j)
#pragma unroll
            for (int t = 0; t < 4; ++t) d[i][j][t] = 0.0f;
    float4 mass4 = make_float4(0.f, 0.f, 0.f, 0.f);
    float4 wy4 = make_float4(0.f, 0.f, 0.f, 0.f);

    auto stage = [&](int ci, int buf) {
        int n0 = ci * 64;
        // A raw: 64 rows x 512B
#pragma unroll
        for (int r = 0; r < 8; ++r) {
            int cid = tid + 256 * r;
            int row = cid >> 5, cc = cid & 31;
            cp16(sb + SM_RAW + buf * 32768 + row * 512 + cc * 16,
                 membership + (size_t)(n0 + row) * M_DIM + m0 + cc * 4);
        }
        // B: Bt[c][qpair]: 128 rows x 144B (32 u32 + pad)
        int np0 = n0 >> 1;
#pragma unroll
        for (int r = 0; r < 4; ++r) {
            int idx = tid + 256 * r;
            int c = idx >> 3, blk = idx & 7;
            cp16(sb + SM_B + buf * 18432 + c * 144 + blk * 16,
                 gT2 + (size_t)c * (N_SAMPLES / 2) + np0 + blk * 4);
        }
        if (tid < 16)
            cp16(sb + SM_Y + buf * 256 + tid * 16, gYsq + n0 + tid * 4);
    };

    stage(cbase, 0);
    asm volatile("cp.async.commit_group;\n");

    for (int it = 0; it < ccnt; ++it) {
        int cur = it & 1;
        if (it + 1 < ccnt) {
            stage(cbase + it + 1, cur ^ 1);
            asm volatile("cp.async.commit_group;\n");
            asm volatile("cp.async.wait_group 1;\n");
        } else {
            asm volatile("cp.async.wait_group 0;\n");
        }
        __syncthreads();

        const char* rawb = smem + SM_RAW + cur * 32768;
        const float* Ys = (const float*)(smem + SM_Y + cur * 256);

        // ---- convert pass: read fp32, fuse mass/wy, pack bf16 ----
        uint32_t pk[16];
#pragma unroll
        for (int q4 = 0; q4 < 4; ++q4) {
            int kr = qg * 8 + q4 * 2;
            float4 v0 = *(const float4*)(rawb + kr * 512 + m4 * 16);
            float4 v1 = *(const float4*)(rawb + (kr + 1) * 512 + m4 * 16);
            float y0 = Ys[kr], y1 = Ys[kr + 1];
            mass4.x += v0.x + v1.x;  wy4.x += v0.x * y0 + v1.x * y1;
            mass4.y += v0.y + v1.y;  wy4.y += v0.y * y0 + v1.y * y1;
            mass4.z += v0.z + v1.z;  wy4.z += v0.z * y0 + v1.z * y1;
            mass4.w += v0.w + v1.w;  wy4.w += v0.w * y0 + v1.w * y1;
            pk[q4 * 4 + 0] = pack_bf16x2(v0.x, v1.x);
            pk[q4 * 4 + 1] = pack_bf16x2(v0.y, v1.y);
            pk[q4 * 4 + 2] = pack_bf16x2(v0.z, v1.z);
            pk[q4 * 4 + 3] = pack_bf16x2(v0.w, v1.w);
        }
        __syncthreads();   // raw reads complete before in-place overwrite

        // Apack [32][136] u32 aliases the current raw buffer
        uint32_t apb = sb + SM_RAW + cur * 32768;
#pragma unroll
        for (int q4 = 0; q4 < 4; ++q4) {
            asm volatile("st.shared.v4.b32 [%0], {%1,%2,%3,%4};"
                :: "r"(apb + (qg * 4 + q4) * 544 + m4 * 16),
                   "r"(pk[q4 * 4 + 0]), "r"(pk[q4 * 4 + 1]),
                   "r"(pk[q4 * 4 + 2]), "r"(pk[q4 * 4 + 3]));
        }
        __syncthreads();

        // ---- MMA pass ----
        const uint32_t* Ap = (const uint32_t*)(smem + SM_RAW + cur * 32768);
        uint32_t bbase = sb + SM_B + cur * 18432 + (c_off + lane) * 144;
#pragma unroll
        for (int ks = 0; ks < 4; ++ks) {
            int qb = ks * 8;
            uint32_t af[2][4];
#pragma unroll
            for (int mt2 = 0; mt2 < 2; ++mt2) {
                int mr = m_off + mt2 * 16 + lr;
                af[mt2][0] = Ap[(qb + lc) * 136 + mr];
                af[mt2][1] = Ap[(qb + lc) * 136 + mr + 8];
                af[mt2][2] = Ap[(qb + 4 + lc) * 136 + mr];
                af[mt2][3] = Ap[(qb + 4 + lc) * 136 + mr + 8];
            }
            uint32_t bA[4], bB[4];
            // ct 0-3 (c rows c_off .. c_off+31)
            ldm_x4(bA, bbase + ks * 32);
            ldm_x4(bB, bbase + ks * 32 + 16);
#pragma unroll
            for (int j = 0; j < 4; ++j) {
                mma_bf16(d[0][j], af[0], bA[j], bB[j]);
                mma_bf16(d[1][j], af[1], bA[j], bB[j]);
            }
            // ct 4-7 (c rows c_off+32 .. c_off+63)
            ldm_x4(bA, bbase + 4608 + ks * 32);
            ldm_x4(bB, bbase + 4608 + ks * 32 + 16);
#pragma unroll
            for (int j = 0; j < 4; ++j) {
                mma_bf16(d[0][4 + j], af[0], bA[j], bB[j]);
                mma_bf16(d[1][4 + j], af[1], bA[j], bB[j]);
            }
        }
        __syncthreads();
    }

    // ---- epilogue: mass/wy reduction (raw buffers free now) ----
    float* redM = (float*)(smem + SM_RAW);
    float* redW = (float*)(smem + SM_RAW + 4096);
    *(float4*)(redM + qg * 128 + m4 * 4) = mass4;
    *(float4*)(redW + qg * 128 + m4 * 4) = wy4;
    __syncthreads();
    if (tid < 128) {
        float sM = 0.f, sW = 0.f;
#pragma unroll
        for (int g = 0; g < 8; ++g) {
            sM += redM[g * 128 + tid];
            sW += redW[g * 128 + tid];
        }
        atomicAdd(&gMass[m0 + tid], sM);
        atomicAdd(&gWy[m0 + tid], sW);
    }

#pragma unroll
    for (int mt2 = 0; mt2 < 2; ++mt2) {
#pragma unroll
        for (int ct = 0; ct < 8; ++ct) {
#pragma unroll
            for (int i = 0; i < 4; ++i) {
                int row = m0 + m_off + mt2 * 16 + lr + ((i >> 1) * 8);
                int col = c_off + ct * 8 + lc * 2 + (i & 1);
                atomicAdd(&gS[(size_t)row * C_DIM + col], d[mt2][ct][i]);
            }
        }
    }
}

// ---------------- Kernel 2: per-feature finalize + fused writeout ----------------
__global__ void k2_finalize(float* out, int out_size) {
    __shared__ float cent[K_BINS][C_DIM];
    __shared__ float s_csq[K_BINS];
    __shared__ float wRep[8];
    __shared__ float wInt[8];

    int f = blockIdx.x;
    int tid = threadIdx.x;
    int w = tid >> 5, lane = tid & 31;

    for (int idx = tid; idx < K_BINS * C_DIM; idx += 256) {
        int k = idx >> 7;
        int c = idx & 127;
        float bm = gMass[f * K_BINS + k] + EPSV;
        cent[k][c] = gS[(size_t)(f * K_BINS + k) * C_DIM + c] / bm;
    }
    __syncthreads();

    for (int k = w; k < K_BINS; k += 8) {
        float s = 0.0f;
#pragma unroll
        for (int j = 0; j < 4; ++j) {
            float v = cent[k][lane + 32 * j];
            s += v * v;
        }
        s = warp_sum(s);
        if (lane == 0) s_csq[k] = s;
    }
    __syncthreads();

    if (w == 0) {
        int k = lane;
        float bm = gMass[f * K_BINS + k] + EPSV;
        float wv = gWy[f * K_BINS + k] / bm - s_csq[k] * (1.0f + EPSV / bm);
        float p = bm / (float)N_SAMPLES;
        float ent = p * logf(p + EPSV);
        float dsum = warp_sum(wv);
        float esum = warp_sum(ent);
        if (lane == 0) {
            atomicAdd(&gOut[0], dsum);
            atomicAdd(&gOut[1], esum);
        }
    }

    float repP = 0.0f;
    for (int p = w; p < K_BINS - 1; p += 8) {
        float s = 0.0f;
#pragma unroll
        for (int j = 0; j < 4; ++j) {
            int c = lane + 32 * j;
            float dd = cent[p][c] - cent[p + 1][c];
            s += dd * dd;
        }
        s = warp_sum(s);
        if (lane == 0) repP += expf(-s);
    }

    float intP = 0.0f;
    for (int k = 0; k < K_BINS - 1; ++k) {
        for (int j = k + 1 + w; j < K_BINS; j += 8) {
            float s = 0.0f;
#pragma unroll
            for (int jj = 0; jj < 4; ++jj) {
                int c = lane + 32 * jj;
                float dd = cent[k][c] - cent[j][c];
                s += dd * dd;
            }
            s = warp_sum(s);
            if (lane == 0) intP += expf(-s);
        }
    }
    if (lane == 0) { wRep[w] = repP; wInt[w] = intP; }
    __syncthreads();

    if (tid == 0) {
        float rep = 0.0f, inter = 0.0f;
        for (int i = 0; i < 8; ++i) { rep += wRep[i]; inter += wInt[i]; }
        atomicAdd(&gOut[2], rep);
        atomicAdd(&gOut[3], inter);
        __threadfence();
        int done = atomicAdd(&gDone, 1);
        if (done == F_DIM - 1) {
            float disp  = atomicAdd(&gOut[0], 0.0f);
            float ent   = atomicAdd(&gOut[1], 0.0f);
            float repT  = atomicAdd(&gOut[2], 0.0f);
            float intT  = atomicAdd(&gOut[3], 0.0f) / (float)F_DIM;
            float total = disp + 0.1f * ent + 0.5f * repT + 0.3f * intT;
            float vals[5] = {total, disp, ent, repT, intT};
            for (int i = 0; i < out_size; ++i) out[i] = (i < 5) ? vals[i] : 0.0f;
        }
    }
}

extern "C" void kernel_launch(void* const* d_in, const int* in_sizes, int n_in,
                              void* d_out, int out_size) {
    const float* p0 = (const float*)d_in[0];
    const float* p1 = (const float*)d_in[1];
    const float* membership = p0;
    const float* teacher = p1;
    if (n_in >= 2 && in_sizes[0] < in_sizes[1]) {
        membership = p1;
        teacher = p0;
    }
    cudaFuncSetAttribute(k1_main, cudaFuncAttributeMaxDynamicSharedMemorySize, SM_TOTAL);
    cudaFuncSetAttribute(k1_main, cudaFuncAttributePreferredSharedMemoryCarveout, 100);
    k0_init<<<2048, 256>>>(teacher);
    k0b_transpose<<<1024, 256>>>();
    k1_main<<<296, 256, SM_TOTAL>>>(membership);
    k2_finalize<<<F_DIM, 256>>>((float*)d_out, out_size);
}

// round 16
// speedup vs baseline: 1.7094x; 1.7094x over previous
#include <cuda_runtime.h>
#include <cuda_bf16.h>
#include <math.h>
#include <stdint.h>

#define N_SAMPLES 16384
#define F_DIM 64
#define K_BINS 32
#define M_DIM 2048
#define C_DIM 128
#define EPSV 1e-8f
#define SPLITS 16
#define L_CHUNK 1024
#define NIT 16             // 16 chunks x 64 samples

// ---- k1 dynamic smem layout (bytes) ----
#define SM_RAW   0
#define SM_B     65536
#define SM_Y     100352
#define SM_TOTAL 100864

__device__ float    gS[M_DIM * C_DIM];
__device__ float    gMass[M_DIM];
__device__ float    gWy[M_DIM];
__device__ float    gYsq[N_SAMPLES];
__device__ uint32_t gTpack[(N_SAMPLES / 2) * C_DIM];
__device__ float    gOut[4];
__device__ int      gDone;

__device__ __forceinline__ float warp_sum(float v) {
    v += __shfl_xor_sync(0xffffffffu, v, 16);
    v += __shfl_xor_sync(0xffffffffu, v, 8);
    v += __shfl_xor_sync(0xffffffffu, v, 4);
    v += __shfl_xor_sync(0xffffffffu, v, 2);
    v += __shfl_xor_sync(0xffffffffu, v, 1);
    return v;
}
__device__ __forceinline__ uint32_t pack_bf16x2(float lo, float hi) {
    __nv_bfloat162 t = __floats2bfloat162_rn(lo, hi);
    return *reinterpret_cast<uint32_t*>(&t);
}
__device__ __forceinline__ void mma_bf16(float* d, const uint32_t* a,
                                         uint32_t b0, uint32_t b1) {
    asm volatile(
        "mma.sync.aligned.m16n8k16.row.col.f32.bf16.bf16.f32 "
        "{%0,%1,%2,%3}, {%4,%5,%6,%7}, {%8,%9}, {%0,%1,%2,%3};\n"
        : "+f"(d[0]), "+f"(d[1]), "+f"(d[2]), "+f"(d[3])
        : "r"(a[0]), "r"(a[1]), "r"(a[2]), "r"(a[3]), "r"(b0), "r"(b1));
}
__device__ __forceinline__ void cp16(uint32_t dst, const void* src) {
    asm volatile("cp.async.cg.shared.global [%0], [%1], 16;\n" :: "r"(dst), "l"(src));
}

// ---------------- Kernel 0: zero + y_sq + prepack teacher ----------------
__global__ void k0_init(const float* __restrict__ teacher) {
    int tid = threadIdx.x;
    int idx = blockIdx.x * 256 + tid;            // 0 .. 524287
    if (idx < M_DIM * C_DIM) gS[idx] = 0.0f;
    if (idx < M_DIM) { gMass[idx] = 0.0f; gWy[idx] = 0.0f; }
    if (idx < 4) gOut[idx] = 0.0f;
    if (idx == 4) gDone = 0;

    int n = idx >> 5;
    int lane = tid & 31;
    if (n < N_SAMPLES) {
        float4 v = reinterpret_cast<const float4*>(teacher)[n * 32 + lane];
        float s = v.x * v.x + v.y * v.y + v.z * v.z + v.w * v.w;
        s = warp_sum(s);
        if (lane == 0) gYsq[n] = s;
    }

#pragma unroll
    for (int j = 0; j < 2; ++j) {
        int w = idx + j * 524288;
        int np = w >> 7;
        int c = w & 127;
        gTpack[w] = pack_bf16x2(teacher[(2 * np) * C_DIM + c],
                                teacher[(2 * np + 1) * C_DIM + c]);
    }
}

// ---------------- Kernel 1: convert-pass bf16-MMA GEMM + fused mass/wy ----------------
// (byte-exact R14 design: 256 CTAs, 2/SM, 64-sample chunks)
__global__ void __launch_bounds__(256, 2)
k1_main(const float* __restrict__ membership) {
    extern __shared__ char smem[];
    uint32_t sb = (uint32_t)__cvta_generic_to_shared(smem);

    int tid = threadIdx.x;
    int mt = blockIdx.x & 15;
    int sp = blockIdx.x >> 4;
    int m0 = mt * 128;
    int nbeg = sp * L_CHUNK;

    int w = tid >> 5, lane = tid & 31;
    int m_off = (w & 3) * 32;
    int c_off = (w >> 2) * 64;
    int lr = lane >> 2, lc = lane & 3;

    int m4 = tid & 31;
    int qg = tid >> 5;

    float d[2][8][4];
#pragma unroll
    for (int i = 0; i < 2; ++i)
#pragma unroll
        for (int j = 0; j < 8; ++j)
#pragma unroll
            for (int t = 0; t < 4; ++t) d[i][j][t] = 0.0f;
    float4 mass4 = make_float4(0.f, 0.f, 0.f, 0.f);
    float4 wy4 = make_float4(0.f, 0.f, 0.f, 0.f);

    auto stage = [&](int it, int buf) {
        int n0 = nbeg + it * 64;
#pragma unroll
        for (int r = 0; r < 8; ++r) {
            int cid = tid + 256 * r;
            int row = cid >> 5, cc = cid & 31;
            cp16(sb + SM_RAW + buf * 32768 + row * 512 + cc * 16,
                 membership + (size_t)(n0 + row) * M_DIM + m0 + cc * 4);
        }
        int np0 = n0 >> 1;
#pragma unroll
        for (int r = 0; r < 4; ++r) {
            int cid = tid + 256 * r;
            int row = cid >> 5, cc = cid & 31;
            cp16(sb + SM_B + buf * 17408 + row * 544 + cc * 16,
                 gTpack + (size_t)(np0 + row) * C_DIM + cc * 4);
        }
        if (tid < 16)
            cp16(sb + SM_Y + buf * 256 + tid * 16, gYsq + n0 + tid * 4);
    };

    stage(0, 0);
    asm volatile("cp.async.commit_group;\n");

    for (int it = 0; it < NIT; ++it) {
        int cur = it & 1;
        if (it + 1 < NIT) {
            stage(it + 1, cur ^ 1);
            asm volatile("cp.async.commit_group;\n");
            asm volatile("cp.async.wait_group 1;\n");
        } else {
            asm volatile("cp.async.wait_group 0;\n");
        }
        __syncthreads();

        const char* rawb = smem + SM_RAW + cur * 32768;
        const float* Ys = (const float*)(smem + SM_Y + cur * 256);

        uint32_t pk[16];
#pragma unroll
        for (int q4 = 0; q4 < 4; ++q4) {
            int kr = qg * 8 + q4 * 2;
            float4 v0 = *(const float4*)(rawb + kr * 512 + m4 * 16);
            float4 v1 = *(const float4*)(rawb + (kr + 1) * 512 + m4 * 16);
            float y0 = Ys[kr], y1 = Ys[kr + 1];
            mass4.x += v0.x + v1.x;  wy4.x += v0.x * y0 + v1.x * y1;
            mass4.y += v0.y + v1.y;  wy4.y += v0.y * y0 + v1.y * y1;
            mass4.z += v0.z + v1.z;  wy4.z += v0.z * y0 + v1.z * y1;
            mass4.w += v0.w + v1.w;  wy4.w += v0.w * y0 + v1.w * y1;
            pk[q4 * 4 + 0] = pack_bf16x2(v0.x, v1.x);
            pk[q4 * 4 + 1] = pack_bf16x2(v0.y, v1.y);
            pk[q4 * 4 + 2] = pack_bf16x2(v0.z, v1.z);
            pk[q4 * 4 + 3] = pack_bf16x2(v0.w, v1.w);
        }
        __syncthreads();

        uint32_t apb = sb + SM_RAW + cur * 32768;
#pragma unroll
        for (int q4 = 0; q4 < 4; ++q4) {
            asm volatile("st.shared.v4.b32 [%0], {%1,%2,%3,%4};"
                :: "r"(apb + (qg * 4 + q4) * 544 + m4 * 16),
                   "r"(pk[q4 * 4 + 0]), "r"(pk[q4 * 4 + 1]),
                   "r"(pk[q4 * 4 + 2]), "r"(pk[q4 * 4 + 3]));
        }
        __syncthreads();

        const uint32_t* Ap = (const uint32_t*)(smem + SM_RAW + cur * 32768);
        const uint32_t* Bs = (const uint32_t*)(smem + SM_B + cur * 17408);
#pragma unroll
        for (int ks = 0; ks < 4; ++ks) {
            int qb = ks * 8;
            uint32_t af[2][4];
#pragma unroll
            for (int mt2 = 0; mt2 < 2; ++mt2) {
                int mr = m_off + mt2 * 16 + lr;
                af[mt2][0] = Ap[(qb + lc) * 136 + mr];
                af[mt2][1] = Ap[(qb + lc) * 136 + mr + 8];
                af[mt2][2] = Ap[(qb + 4 + lc) * 136 + mr];
                af[mt2][3] = Ap[(qb + 4 + lc) * 136 + mr + 8];
            }
#pragma unroll
            for (int ct = 0; ct < 8; ++ct) {
                int cr = c_off + ct * 8 + lr;
                uint32_t b0 = Bs[(qb + lc) * 136 + cr];
                uint32_t b1 = Bs[(qb + 4 + lc) * 136 + cr];
                mma_bf16(d[0][ct], af[0], b0, b1);
                mma_bf16(d[1][ct], af[1], b0, b1);
            }
        }
        __syncthreads();
    }

    float* redM = (float*)(smem + SM_RAW);
    float* redW = (float*)(smem + SM_RAW + 4096);
    *(float4*)(redM + qg * 128 + m4 * 4) = mass4;
    *(float4*)(redW + qg * 128 + m4 * 4) = wy4;
    __syncthreads();
    if (tid < 128) {
        float sM = 0.f, sW = 0.f;
#pragma unroll
        for (int g = 0; g < 8; ++g) {
            sM += redM[g * 128 + tid];
            sW += redW[g * 128 + tid];
        }
        atomicAdd(&gMass[m0 + tid], sM);
        atomicAdd(&gWy[m0 + tid], sW);
    }

#pragma unroll
    for (int mt2 = 0; mt2 < 2; ++mt2) {
#pragma unroll
        for (int ct = 0; ct < 8; ++ct) {
#pragma unroll
            for (int i = 0; i < 4; ++i) {
                int row = m0 + m_off + mt2 * 16 + lr + ((i >> 1) * 8);
                int col = c_off + ct * 8 + lc * 2 + (i & 1);
                atomicAdd(&gS[(size_t)row * C_DIM + col], d[mt2][ct][i]);
            }
        }
    }
}

// ---------------- Kernel 2: parallelized finalize (4 blocks per feature) ----------------
__global__ void __launch_bounds__(256) k2_finalize(float* out, int out_size) {
    __shared__ float cent[K_BINS][C_DIM];
    __shared__ float s_csq[K_BINS];
    __shared__ float wRep[8];
    __shared__ float wInt[8];

    int bid = blockIdx.x;
    int f = bid >> 2, part = bid & 3;
    int tid = threadIdx.x;
    int w = tid >> 5, lane = tid & 31;
    int slot = part * 8 + w;           // 0..31 global warp-slot for this f

    for (int idx = tid; idx < K_BINS * C_DIM; idx += 256) {
        int k = idx >> 7;
        int c = idx & 127;
        float bm = gMass[f * K_BINS + k] + EPSV;
        cent[k][c] = gS[(size_t)(f * K_BINS + k) * C_DIM + c] / bm;
    }
    __syncthreads();

    for (int k = w; k < K_BINS; k += 8) {
        float s = 0.0f;
#pragma unroll
        for (int j = 0; j < 4; ++j) {
            float v = cent[k][lane + 32 * j];
            s += v * v;
        }
        s = warp_sum(s);
        if (lane == 0) s_csq[k] = s;
    }
    __syncthreads();

    // dispersion + entropy: part 0, warp 0 only
    if (part == 0 && w == 0) {
        int k = lane;
        float bm = gMass[f * K_BINS + k] + EPSV;
        float wv = gWy[f * K_BINS + k] / bm - s_csq[k] * (1.0f + EPSV / bm);
        float p = bm / (float)N_SAMPLES;
        float ent = p * logf(p + EPSV);
        float dsum = warp_sum(wv);
        float esum = warp_sum(ent);
        if (lane == 0) {
            atomicAdd(&gOut[0], dsum);
            atomicAdd(&gOut[1], esum);
        }
    }

    float repP = 0.0f, intP = 0.0f;

    // repulsion: slot s handles adjacent pair (s, s+1), s < 31
    if (slot < K_BINS - 1) {
        int p = slot;
        float s = 0.0f;
#pragma unroll
        for (int j = 0; j < 4; ++j) {
            int c = lane + 32 * j;
            float dd = cent[p][c] - cent[p + 1][c];
            s += dd * dd;
        }
        s = warp_sum(s);
        if (lane == 0) repP = __expf(-s);
    }

    // inter-bin: pair (k, k+1+((slot+k)&31)) when valid -> each pair exactly once
    for (int k = 0; k < K_BINS - 1; ++k) {
        int j = k + 1 + ((slot + k) & 31);
        if (j < K_BINS) {
            float s = 0.0f;
#pragma unroll
            for (int jj = 0; jj < 4; ++jj) {
                int c = lane + 32 * jj;
                float dd = cent[k][c] - cent[j][c];
                s += dd * dd;
            }
            s = warp_sum(s);
            if (lane == 0) intP += __expf(-s);
        }
    }
    if (lane == 0) { wRep[w] = repP; wInt[w] = intP; }
    __syncthreads();

    if (tid == 0) {
        float rep = 0.0f, inter = 0.0f;
        for (int i = 0; i < 8; ++i) { rep += wRep[i]; inter += wInt[i]; }
        atomicAdd(&gOut[2], rep);
        atomicAdd(&gOut[3], inter);
        __threadfence();
        int done = atomicAdd(&gDone, 1);
        if (done == 4 * F_DIM - 1) {
            float disp  = atomicAdd(&gOut[0], 0.0f);
            float ent   = atomicAdd(&gOut[1], 0.0f);
            float repT  = atomicAdd(&gOut[2], 0.0f);
            float intT  = atomicAdd(&gOut[3], 0.0f) / (float)F_DIM;
            float total = disp + 0.1f * ent + 0.5f * repT + 0.3f * intT;
            float vals[5] = {total, disp, ent, repT, intT};
            for (int i = 0; i < out_size; ++i) out[i] = (i < 5) ? vals[i] : 0.0f;
        }
    }
}

extern "C" void kernel_launch(void* const* d_in, const int* in_sizes, int n_in,
                              void* d_out, int out_size) {
    const float* p0 = (const float*)d_in[0];
    const float* p1 = (const float*)d_in[1];
    const float* membership = p0;
    const float* teacher = p1;
    if (n_in >= 2 && in_sizes[0] < in_sizes[1]) {
        membership = p1;
        teacher = p0;
    }
    cudaFuncSetAttribute(k1_main, cudaFuncAttributeMaxDynamicSharedMemorySize, SM_TOTAL);
    cudaFuncSetAttribute(k1_main, cudaFuncAttributePreferredSharedMemoryCarveout, 100);
    k0_init<<<2048, 256>>>(teacher);
    k1_main<<<SPLITS * 16, 256, SM_TOTAL>>>(membership);
    k2_finalize<<<4 * F_DIM, 256>>>((float*)d_out, out_size);
}

// round 17
// speedup vs baseline: 1.7650x; 1.0325x over previous
#include <cuda_runtime.h>
#include <cuda_bf16.h>
#include <math.h>
#include <stdint.h>

#define N_SAMPLES 16384
#define F_DIM 64
#define K_BINS 32
#define M_DIM 2048
#define C_DIM 128
#define EPSV 1e-8f

// ---- k1 dynamic smem layout (bytes) ----
#define SM_RAW   0
#define SM_B     65536
#define SM_Y     100352
#define SM_TOTAL 100864

__device__ float    gS[M_DIM * C_DIM];
__device__ float    gMass[M_DIM];
__device__ float    gWy[M_DIM];
__device__ float    gYsq[N_SAMPLES];
__device__ uint32_t gTpack[(N_SAMPLES / 2) * C_DIM];
__device__ float    gOut[4];
__device__ int      gDone;

__device__ __forceinline__ float warp_sum(float v) {
    v += __shfl_xor_sync(0xffffffffu, v, 16);
    v += __shfl_xor_sync(0xffffffffu, v, 8);
    v += __shfl_xor_sync(0xffffffffu, v, 4);
    v += __shfl_xor_sync(0xffffffffu, v, 2);
    v += __shfl_xor_sync(0xffffffffu, v, 1);
    return v;
}
__device__ __forceinline__ uint32_t pack_bf16x2(float lo, float hi) {
    __nv_bfloat162 t = __floats2bfloat162_rn(lo, hi);
    return *reinterpret_cast<uint32_t*>(&t);
}
__device__ __forceinline__ void mma_bf16(float* d, const uint32_t* a,
                                         uint32_t b0, uint32_t b1) {
    asm volatile(
        "mma.sync.aligned.m16n8k16.row.col.f32.bf16.bf16.f32 "
        "{%0,%1,%2,%3}, {%4,%5,%6,%7}, {%8,%9}, {%0,%1,%2,%3};\n"
        : "+f"(d[0]), "+f"(d[1]), "+f"(d[2]), "+f"(d[3])
        : "r"(a[0]), "r"(a[1]), "r"(a[2]), "r"(a[3]), "r"(b0), "r"(b1));
}
__device__ __forceinline__ void cp16(uint32_t dst, const void* src) {
    asm volatile("cp.async.cg.shared.global [%0], [%1], 16;\n" :: "r"(dst), "l"(src));
}

// ---------------- Kernel 0: zero + y_sq + prepack teacher ----------------
__global__ void k0_init(const float* __restrict__ teacher) {
    int tid = threadIdx.x;
    int idx = blockIdx.x * 256 + tid;            // 0 .. 524287
    if (idx < M_DIM * C_DIM) gS[idx] = 0.0f;
    if (idx < M_DIM) { gMass[idx] = 0.0f; gWy[idx] = 0.0f; }
    if (idx < 4) gOut[idx] = 0.0f;
    if (idx == 4) gDone = 0;

    int n = idx >> 5;
    int lane = tid & 31;
    if (n < N_SAMPLES) {
        float4 v = reinterpret_cast<const float4*>(teacher)[n * 32 + lane];
        float s = v.x * v.x + v.y * v.y + v.z * v.z + v.w * v.w;
        s = warp_sum(s);
        if (lane == 0) gYsq[n] = s;
    }

#pragma unroll
    for (int j = 0; j < 2; ++j) {
        int w = idx + j * 524288;
        int np = w >> 7;
        int c = w & 127;
        gTpack[w] = pack_bf16x2(teacher[(2 * np) * C_DIM + c],
                                teacher[(2 * np + 1) * C_DIM + c]);
    }
}

// ---------------- Kernel 1: convert-pass bf16-MMA GEMM + fused mass/wy ----------------
// grid 296 = 148 SMs x 2 CTAs. Chunk ranges partition 256 chunks per m-tile evenly.
__global__ void __launch_bounds__(256, 2)
k1_main(const float* __restrict__ membership) {
    extern __shared__ char smem[];
    uint32_t sb = (uint32_t)__cvta_generic_to_shared(smem);

    int tid = threadIdx.x;
    int mt = blockIdx.x & 15;
    int sp = blockIdx.x >> 4;
    int m0 = mt * 128;

    int cbase, ccnt;
    if (mt < 8) {   // 19 CTAs per m-tile: 9x14 + 10x13 = 256
        cbase = sp * 13 + min(sp, 9);
        ccnt = 13 + (sp < 9 ? 1 : 0);
    } else {        // 18 CTAs per m-tile: 4x15 + 14x14 = 256
        cbase = sp * 14 + min(sp, 4);
        ccnt = 14 + (sp < 4 ? 1 : 0);
    }

    int w = tid >> 5, lane = tid & 31;
    int m_off = (w & 3) * 32;
    int c_off = (w >> 2) * 64;
    int lr = lane >> 2, lc = lane & 3;

    int m4 = tid & 31;
    int qg = tid >> 5;

    float d[2][8][4];
#pragma unroll
    for (int i = 0; i < 2; ++i)
#pragma unroll
        for (int j = 0; j < 8; ++j)
#pragma unroll
            for (int t = 0; t < 4; ++t) d[i][j][t] = 0.0f;
    float4 mass4 = make_float4(0.f, 0.f, 0.f, 0.f);
    float4 wy4 = make_float4(0.f, 0.f, 0.f, 0.f);

    auto stage = [&](int ci, int buf) {
        int n0 = ci * 64;
#pragma unroll
        for (int r = 0; r < 8; ++r) {
            int cid = tid + 256 * r;
            int row = cid >> 5, cc = cid & 31;
            cp16(sb + SM_RAW + buf * 32768 + row * 512 + cc * 16,
                 membership + (size_t)(n0 + row) * M_DIM + m0 + cc * 4);
        }
        int np0 = n0 >> 1;
#pragma unroll
        for (int r = 0; r < 4; ++r) {
            int cid = tid + 256 * r;
            int row = cid >> 5, cc = cid & 31;
            cp16(sb + SM_B + buf * 17408 + row * 544 + cc * 16,
                 gTpack + (size_t)(np0 + row) * C_DIM + cc * 4);
        }
        if (tid < 16)
            cp16(sb + SM_Y + buf * 256 + tid * 16, gYsq + n0 + tid * 4);
    };

    stage(cbase, 0);
    asm volatile("cp.async.commit_group;\n");

    for (int it = 0; it < ccnt; ++it) {
        int cur = it & 1;
        if (it + 1 < ccnt) {
            stage(cbase + it + 1, cur ^ 1);
            asm volatile("cp.async.commit_group;\n");
            asm volatile("cp.async.wait_group 1;\n");
        } else {
            asm volatile("cp.async.wait_group 0;\n");
        }
        __syncthreads();

        const char* rawb = smem + SM_RAW + cur * 32768;
        const float* Ys = (const float*)(smem + SM_Y + cur * 256);

        uint32_t pk[16];
#pragma unroll
        for (int q4 = 0; q4 < 4; ++q4) {
            int kr = qg * 8 + q4 * 2;
            float4 v0 = *(const float4*)(rawb + kr * 512 + m4 * 16);
            float4 v1 = *(const float4*)(rawb + (kr + 1) * 512 + m4 * 16);
            float y0 = Ys[kr], y1 = Ys[kr + 1];
            mass4.x += v0.x + v1.x;  wy4.x += v0.x * y0 + v1.x * y1;
            mass4.y += v0.y + v1.y;  wy4.y += v0.y * y0 + v1.y * y1;
            mass4.z += v0.z + v1.z;  wy4.z += v0.z * y0 + v1.z * y1;
            mass4.w += v0.w + v1.w;  wy4.w += v0.w * y0 + v1.w * y1;
            pk[q4 * 4 + 0] = pack_bf16x2(v0.x, v1.x);
            pk[q4 * 4 + 1] = pack_bf16x2(v0.y, v1.y);
            pk[q4 * 4 + 2] = pack_bf16x2(v0.z, v1.z);
            pk[q4 * 4 + 3] = pack_bf16x2(v0.w, v1.w);
        }
        __syncthreads();

        uint32_t apb = sb + SM_RAW + cur * 32768;
#pragma unroll
        for (int q4 = 0; q4 < 4; ++q4) {
            asm volatile("st.shared.v4.b32 [%0], {%1,%2,%3,%4};"
                :: "r"(apb + (qg * 4 + q4) * 544 + m4 * 16),
                   "r"(pk[q4 * 4 + 0]), "r"(pk[q4 * 4 + 1]),
                   "r"(pk[q4 * 4 + 2]), "r"(pk[q4 * 4 + 3]));
        }
        __syncthreads();

        const uint32_t* Ap = (const uint32_t*)(smem + SM_RAW + cur * 32768);
        const uint32_t* Bs = (const uint32_t*)(smem + SM_B + cur * 17408);
#pragma unroll
        for (int ks = 0; ks < 4; ++ks) {
            int qb = ks * 8;
            uint32_t af[2][4];
#pragma unroll
            for (int mt2 = 0; mt2 < 2; ++mt2) {
                int mr = m_off + mt2 * 16 + lr;
                af[mt2][0] = Ap[(qb + lc) * 136 + mr];
                af[mt2][1] = Ap[(qb + lc) * 136 + mr + 8];
                af[mt2][2] = Ap[(qb + 4 + lc) * 136 + mr];
                af[mt2][3] = Ap[(qb + 4 + lc) * 136 + mr + 8];
            }
#pragma unroll
            for (int ct = 0; ct < 8; ++ct) {
                int cr = c_off + ct * 8 + lr;
                uint32_t b0 = Bs[(qb + lc) * 136 + cr];
                uint32_t b1 = Bs[(qb + 4 + lc) * 136 + cr];
                mma_bf16(d[0][ct], af[0], b0, b1);
                mma_bf16(d[1][ct], af[1], b0, b1);
            }
        }
        __syncthreads();
    }

    float* redM = (float*)(smem + SM_RAW);
    float* redW = (float*)(smem + SM_RAW + 4096);
    *(float4*)(redM + qg * 128 + m4 * 4) = mass4;
    *(float4*)(redW + qg * 128 + m4 * 4) = wy4;
    __syncthreads();
    if (tid < 128) {
        float sM = 0.f, sW = 0.f;
#pragma unroll
        for (int g = 0; g < 8; ++g) {
            sM += redM[g * 128 + tid];
            sW += redW[g * 128 + tid];
        }
        atomicAdd(&gMass[m0 + tid], sM);
        atomicAdd(&gWy[m0 + tid], sW);
    }

#pragma unroll
    for (int mt2 = 0; mt2 < 2; ++mt2) {
#pragma unroll
        for (int ct = 0; ct < 8; ++ct) {
#pragma unroll
            for (int i = 0; i < 4; ++i) {
                int row = m0 + m_off + mt2 * 16 + lr + ((i >> 1) * 8);
                int col = c_off + ct * 8 + lc * 2 + (i & 1);
                atomicAdd(&gS[(size_t)row * C_DIM + col], d[mt2][ct][i]);
            }
        }
    }
}

// ---------------- Kernel 2: parallelized finalize (4 blocks per feature) ----------------
__global__ void __launch_bounds__(256) k2_finalize(float* out, int out_size) {
    __shared__ float cent[K_BINS][C_DIM];
    __shared__ float s_csq[K_BINS];
    __shared__ float wRep[8];
    __shared__ float wInt[8];

    int bid = blockIdx.x;
    int f = bid >> 2, part = bid & 3;
    int tid = threadIdx.x;
    int w = tid >> 5, lane = tid & 31;
    int slot = part * 8 + w;

    for (int idx = tid; idx < K_BINS * C_DIM; idx += 256) {
        int k = idx >> 7;
        int c = idx & 127;
        float bm = gMass[f * K_BINS + k] + EPSV;
        cent[k][c] = gS[(size_t)(f * K_BINS + k) * C_DIM + c] / bm;
    }
    __syncthreads();

    for (int k = w; k < K_BINS; k += 8) {
        float s = 0.0f;
#pragma unroll
        for (int j = 0; j < 4; ++j) {
            float v = cent[k][lane + 32 * j];
            s += v * v;
        }
        s = warp_sum(s);
        if (lane == 0) s_csq[k] = s;
    }
    __syncthreads();

    if (part == 0 && w == 0) {
        int k = lane;
        float bm = gMass[f * K_BINS + k] + EPSV;
        float wv = gWy[f * K_BINS + k] / bm - s_csq[k] * (1.0f + EPSV / bm);
        float p = bm / (float)N_SAMPLES;
        float ent = p * logf(p + EPSV);
        float dsum = warp_sum(wv);
        float esum = warp_sum(ent);
        if (lane == 0) {
            atomicAdd(&gOut[0], dsum);
            atomicAdd(&gOut[1], esum);
        }
    }

    float repP = 0.0f, intP = 0.0f;

    if (slot < K_BINS - 1) {
        int p = slot;
        float s = 0.0f;
#pragma unroll
        for (int j = 0; j < 4; ++j) {
            int c = lane + 32 * j;
            float dd = cent[p][c] - cent[p + 1][c];
            s += dd * dd;
        }
        s = warp_sum(s);
        if (lane == 0) repP = __expf(-s);
    }

    for (int k = 0; k < K_BINS - 1; ++k) {
        int j = k + 1 + ((slot + k) & 31);
        if (j < K_BINS) {
            float s = 0.0f;
#pragma unroll
            for (int jj = 0; jj < 4; ++jj) {
                int c = lane + 32 * jj;
                float dd = cent[k][c] - cent[j][c];
                s += dd * dd;
            }
            s = warp_sum(s);
            if (lane == 0) intP += __expf(-s);
        }
    }
    if (lane == 0) { wRep[w] = repP; wInt[w] = intP; }
    __syncthreads();

    if (tid == 0) {
        float rep = 0.0f, inter = 0.0f;
        for (int i = 0; i < 8; ++i) { rep += wRep[i]; inter += wInt[i]; }
        atomicAdd(&gOut[2], rep);
        atomicAdd(&gOut[3], inter);
        __threadfence();
        int done = atomicAdd(&gDone, 1);
        if (done == 4 * F_DIM - 1) {
            float disp  = atomicAdd(&gOut[0], 0.0f);
            float ent   = atomicAdd(&gOut[1], 0.0f);
            float repT  = atomicAdd(&gOut[2], 0.0f);
            float intT  = atomicAdd(&gOut[3], 0.0f) / (float)F_DIM;
            float total = disp + 0.1f * ent + 0.5f * repT + 0.3f * intT;
            float vals[5] = {total, disp, ent, repT, intT};
            for (int i = 0; i < out_size; ++i) out[i] = (i < 5) ? vals[i] : 0.0f;
        }
    }
}

extern "C" void kernel_launch(void* const* d_in, const int* in_sizes, int n_in,
                              void* d_out, int out_size) {
    const float* p0 = (const float*)d_in[0];
    const float* p1 = (const float*)d_in[1];
    const float* membership = p0;
    const float* teacher = p1;
    if (n_in >= 2 && in_sizes[0] < in_sizes[1]) {
        membership = p1;
        teacher = p0;
    }
    cudaFuncSetAttribute(k1_main, cudaFuncAttributeMaxDynamicSharedMemorySize, SM_TOTAL);
    cudaFuncSetAttribute(k1_main, cudaFuncAttributePreferredSharedMemoryCarveout, 100);
    k0_init<<<2048, 256>>>(teacher);
    k1_main<<<296, 256, SM_TOTAL>>>(membership);
    k2_finalize<<<4 * F_DIM, 256>>>((float*)d_out, out_size);
}